// round 9
// baseline (speedup 1.0000x reference)
#include <cuda_runtime.h>

// Dilated attention, fused rates + dense-load score phase.
// B=4,H=16,T=8192,D=64. One block (512 thr, 16 warps) per (b,h,64-tok window).
// Warp t owns rows 4t..4t+3. Lane: i=lane>>3 (row), kk=lane&7 (key slot).
// Score phase: Q kept in regs strided-d (c=(i&1)*8+kk, d=c+16j); each lane
// computes partial dots for its ROW PAIR over its 4 d-positions; K loaded as
// conflict-free LDS.32 (16 d-classes x 4B, dense); scores assembled via a
// 4-round shfl reduce-scatter ending at lane (i,kk) owning score(row i, key
// 8m+kk) — identical ownership to the old layout, so softmax/PV unchanged.
// Sub-rates reuse union exponentials (masked re-sum, no second expf pass).
//   r1: S=8,  j1=t>>1, active iff j1%2==h%2,        k0=8*j1
//   r2: S=16, j2=t>>2, active iff j2==h%4,          k0=16*j2
//   r3: S=32, j3=t>>3, active iff (2W+j3)%8==h%8,   k0=32*j3
//   r4: S=64, active iff W%16==h%16,                k0=0

#define STRIDE 68   // smem row stride (floats), 16B-aligned, conflict-free

__device__ __forceinline__ void cp16(unsigned int saddr, const float* g) {
    asm volatile("cp.async.cg.shared.global [%0], [%1], 16;\n"
                 :: "r"(saddr), "l"(g));
}

template <int NBP>
__device__ __forceinline__ void seg_multi(
    const float* __restrict__ qs, const float* __restrict__ ks,
    const float* __restrict__ vs, int w_id, int lane, int k0,
    int kA, bool aA, int kB, bool aB, int kC, bool aC, float* acc)
{
    const int i   = lane >> 3;
    const int kk  = lane & 7;
    const int ib  = i & 1;                  // row within pair = lane bit 3
    const int cidx = (ib << 3) | kk;        // d-class 0..15
    const int qr  = (w_id << 2) + i;
    const int rA  = (w_id << 2) + ((i >> 1) << 1);   // pair base row

    // Q in registers (strided-d, dense-ish load, once)
    const float* qpA = qs + rA * STRIDE + cidx;
    const float* qpB = qpA + STRIDE;
    const float qA0 = qpA[0],  qA1 = qpA[16], qA2 = qpA[32], qA3 = qpA[48];
    const float qB0 = qpB[0],  qB1 = qpB[16], qB2 = qpB[32], qB3 = qpB[48];

    // ---- scores via partial dots + reduce-scatter ----
    float sc[NBP];
#pragma unroll
    for (int m = 0; m < NBP; m++) {
        const float* kb = ks + (k0 + 8 * m) * STRIDE + cidx;
        float w8[8];
#pragma unroll
        for (int s = 0; s < 8; s++) {
            const float* kr = kb + s * STRIDE;
            float k0f = kr[0], k1f = kr[16], k2f = kr[32], k3f = kr[48];
            float pa = qA0 * k0f + qA1 * k1f + qA2 * k2f + qA3 * k3f;
            float pb = qB0 * k0f + qB1 * k1f + qB2 * k2f + qB3 * k3f;
            // fold ib round immediately: keep own row, add partner's same-row
            float x = ib ? pb : pa;
            float y = ib ? pa : pb;
            w8[s] = x + __shfl_xor_sync(0xffffffffu, y, 8);
        }
        float w4[4];
#pragma unroll
        for (int j = 0; j < 4; j++) {
            float x = (kk & 4) ? w8[4 + j] : w8[j];
            float y = (kk & 4) ? w8[j]     : w8[4 + j];
            w4[j] = x + __shfl_xor_sync(0xffffffffu, y, 4);
        }
        float w2[2];
#pragma unroll
        for (int j = 0; j < 2; j++) {
            float x = (kk & 2) ? w4[2 + j] : w4[j];
            float y = (kk & 2) ? w4[j]     : w4[2 + j];
            w2[j] = x + __shfl_xor_sync(0xffffffffu, y, 2);
        }
        {
            float x = (kk & 1) ? w2[1] : w2[0];
            float y = (kk & 1) ? w2[0] : w2[1];
            sc[m] = x + __shfl_xor_sync(0xffffffffu, y, 1);
        }
    }

    // ---- causal mask + scale ----
#pragma unroll
    for (int m = 0; m < NBP; m++) {
        int key = k0 + 8 * m + kk;
        sc[m] = (key <= qr) ? sc[m] * 0.125f : -1e30f;
    }

    // ---- union softmax; e[] reused for sub-rates ----
    float wsum[NBP];
    {
        float mx = -1e30f;
#pragma unroll
        for (int m = 0; m < NBP; m++) mx = fmaxf(mx, sc[m]);
        mx = fmaxf(mx, __shfl_xor_sync(0xffffffffu, mx, 1));
        mx = fmaxf(mx, __shfl_xor_sync(0xffffffffu, mx, 2));
        mx = fmaxf(mx, __shfl_xor_sync(0xffffffffu, mx, 4));
        float sum = 0.f;
#pragma unroll
        for (int m = 0; m < NBP; m++) {
            sc[m] = __expf(sc[m] - mx);   // sc[] now holds e[] (masked -> 0)
            sum += sc[m];
        }
        sum += __shfl_xor_sync(0xffffffffu, sum, 1);
        sum += __shfl_xor_sync(0xffffffffu, sum, 2);
        sum += __shfl_xor_sync(0xffffffffu, sum, 4);
        float inv = 1.f / sum;
#pragma unroll
        for (int m = 0; m < NBP; m++) wsum[m] = sc[m] * inv;
    }

    // ---- nested sub-rates: masked re-sum of union exponentials ----
#pragma unroll
    for (int r = 0; r < 3; r++) {
        int  kr = (r == 0) ? kA : (r == 1) ? kB : kC;
        bool ar = (r == 0) ? aA : (r == 1) ? aB : aC;
        if (ar) {
            float s = 0.f;
#pragma unroll
            for (int m = 0; m < NBP; m++) {
                int key = k0 + 8 * m + kk;
                s += (key >= kr) ? sc[m] : 0.f;
            }
            s += __shfl_xor_sync(0xffffffffu, s, 1);
            s += __shfl_xor_sync(0xffffffffu, s, 2);
            s += __shfl_xor_sync(0xffffffffu, s, 4);
            float inv = 1.f / s;
#pragma unroll
            for (int m = 0; m < NBP; m++) {
                int key = k0 + 8 * m + kk;
                if (key >= kr) wsum[m] += sc[m] * inv;
            }
        }
    }

    // ---- PV: lane accumulates its d-eighth of its row (unchanged) ----
    const int srcbase = lane & ~7;
    const float* vbase = vs + k0 * STRIDE + kk * 8;
#pragma unroll 4
    for (int c = 0; c < NBP * 8; c++) {
        float p = __shfl_sync(0xffffffffu, wsum[c >> 3], srcbase | (c & 7));
        const float* vr = vbase + c * STRIDE;
        float4 v0 = *reinterpret_cast<const float4*>(vr);
        float4 v1 = *reinterpret_cast<const float4*>(vr + 4);
        acc[0] += p * v0.x; acc[1] += p * v0.y;
        acc[2] += p * v0.z; acc[3] += p * v0.w;
        acc[4] += p * v1.x; acc[5] += p * v1.y;
        acc[6] += p * v1.z; acc[7] += p * v1.w;
    }
}

#define SMEM_KS (64 * STRIDE)
#define SMEM_VS (2 * 64 * STRIDE)
#define SMEM_FLOATS (3 * 64 * STRIDE)
#define SMEM_BYTES  (SMEM_FLOATS * 4)

__global__ void __launch_bounds__(512, 2)
dilated_attn_kernel(const float* __restrict__ Q, const float* __restrict__ K,
                    const float* __restrict__ V, float* __restrict__ out)
{
    extern __shared__ float smem[];
    float* qs = smem;
    float* ks = smem + SMEM_KS;
    float* vs = smem + SMEM_VS;

    const int wWin = blockIdx.x;
    const int h    = blockIdx.y;
    const int b    = blockIdx.z;
    const int tid  = threadIdx.x;
    const int base = ((b * 16 + h) * 8192 + wWin * 64) * 64;

    const bool r4_act = ((wWin & 15) == (h & 15));

    // cooperative tile load via cp.async.cg, skipping never-touched rows
    {
        unsigned int qa = (unsigned int)__cvta_generic_to_shared(qs);
        unsigned int ka = (unsigned int)__cvta_generic_to_shared(ks);
        unsigned int va = (unsigned int)__cvta_generic_to_shared(vs);
#pragma unroll
        for (int it = 0; it < 2; it++) {
            int idx = tid + it * 512;          // 0..1023 float4s
            int row = idx >> 4;
            int col = (idx & 15) << 2;
            bool need = (((row >> 3) & 1) == (h & 1))
                     || ((row >> 4) == (h & 3))
                     || ((((wWin << 1) + (row >> 5)) & 7) == (h & 7))
                     || r4_act;
            if (need) {
                unsigned int so = (unsigned int)(row * STRIDE + col) * 4u;
                int go = base + row * 64 + col;
                cp16(qa + so, Q + go);
                cp16(ka + so, K + go);
                cp16(va + so, V + go);
            }
        }
        asm volatile("cp.async.commit_group;\n");
        asm volatile("cp.async.wait_group 0;\n");
    }
    __syncthreads();

    const int w_id = tid >> 5;   // 0..15
    const int lane = tid & 31;

    float acc[8];
#pragma unroll
    for (int j = 0; j < 8; j++) acc[j] = 0.f;

    // rate activity (warp-uniform)
    const int j1 = w_id >> 1, j2 = w_id >> 2, j3 = w_id >> 3;
    const bool A1 = (j1 & 1) == (h & 1);
    const bool A2 = j2 == (h & 3);
    const bool A3 = ((((wWin << 1) + j3) & 7) == (h & 7));
    const int k1 = j1 << 3, k2 = j2 << 4, k3 = j3 << 5;

    if (r4_act) {
        switch (w_id >> 1) {
            case 0: seg_multi<1>(qs, ks, vs, w_id, lane, 0, k3, A3, k2, A2, k1, A1, acc); break;
            case 1: seg_multi<2>(qs, ks, vs, w_id, lane, 0, k3, A3, k2, A2, k1, A1, acc); break;
            case 2: seg_multi<3>(qs, ks, vs, w_id, lane, 0, k3, A3, k2, A2, k1, A1, acc); break;
            case 3: seg_multi<4>(qs, ks, vs, w_id, lane, 0, k3, A3, k2, A2, k1, A1, acc); break;
            case 4: seg_multi<5>(qs, ks, vs, w_id, lane, 0, k3, A3, k2, A2, k1, A1, acc); break;
            case 5: seg_multi<6>(qs, ks, vs, w_id, lane, 0, k3, A3, k2, A2, k1, A1, acc); break;
            case 6: seg_multi<7>(qs, ks, vs, w_id, lane, 0, k3, A3, k2, A2, k1, A1, acc); break;
            case 7: seg_multi<8>(qs, ks, vs, w_id, lane, 0, k3, A3, k2, A2, k1, A1, acc); break;
        }
    } else if (A3) {
        switch ((w_id & 7) >> 1) {
            case 0: seg_multi<1>(qs, ks, vs, w_id, lane, k3, k2, A2, k1, A1, 0, false, acc); break;
            case 1: seg_multi<2>(qs, ks, vs, w_id, lane, k3, k2, A2, k1, A1, 0, false, acc); break;
            case 2: seg_multi<3>(qs, ks, vs, w_id, lane, k3, k2, A2, k1, A1, 0, false, acc); break;
            case 3: seg_multi<4>(qs, ks, vs, w_id, lane, k3, k2, A2, k1, A1, 0, false, acc); break;
        }
    } else if (A2) {
        if ((w_id & 3) < 2)
            seg_multi<1>(qs, ks, vs, w_id, lane, k2, k1, A1, 0, false, 0, false, acc);
        else
            seg_multi<2>(qs, ks, vs, w_id, lane, k2, k1, A1, 0, false, 0, false, acc);
    } else if (A1) {
        seg_multi<1>(qs, ks, vs, w_id, lane, k1, 0, false, 0, false, 0, false, acc);
    }

    // write (avg over 4 rates); untouched rows emit zeros
    const int i  = lane >> 3;
    const int kk = lane & 7;
    const int qr = (w_id << 2) + i;
    float* orow = out + base + qr * 64 + kk * 8;
    float4 o0, o1;
    o0.x = acc[0] * 0.25f; o0.y = acc[1] * 0.25f;
    o0.z = acc[2] * 0.25f; o0.w = acc[3] * 0.25f;
    o1.x = acc[4] * 0.25f; o1.y = acc[5] * 0.25f;
    o1.z = acc[6] * 0.25f; o1.w = acc[7] * 0.25f;
    *reinterpret_cast<float4*>(orow)     = o0;
    *reinterpret_cast<float4*>(orow + 4) = o1;
}

extern "C" void kernel_launch(void* const* d_in, const int* in_sizes, int n_in,
                              void* d_out, int out_size)
{
    const float* Q = (const float*)d_in[0];
    const float* K = (const float*)d_in[1];
    const float* V = (const float*)d_in[2];
    float* out = (float*)d_out;

    cudaFuncSetAttribute(dilated_attn_kernel,
                         cudaFuncAttributeMaxDynamicSharedMemorySize, SMEM_BYTES);

    dim3 grid(128, 16, 4);
    dilated_attn_kernel<<<grid, 512, SMEM_BYTES>>>(Q, K, V, out);
}